// round 7
// baseline (speedup 1.0000x reference)
#include <cuda_runtime.h>
#include <cuda_fp16.h>

// RoIAlign via NHWC fp16 relayout + table-driven HFMA2 full-C gather.
// feat: (B=2, C=256, H=200, W=336) fp32 NCHW
// rois: (N=1000, 5) [bidx, x1, y1, x2, y2] fp32
// out:  (N, 256, 7, 7) fp32

#define B_    2
#define C_    256
#define H_    200
#define W_    336
#define OUTH  7
#define OUTW  7
#define NBIN  49
#define HWC   (H_ * W_ * C_)
#define SOUT_STRIDE 268   // halves; multiple of 4 (STS.64 align), 134 words -> 2-way LDS conflict max

// NHWC fp16 scratch: [B][H][W][C]
__device__ __half g_feat16[(size_t)B_ * HWC];

// ---------------------------------------------------------------------------
// Kernel 1: NCHW fp32 -> NHWC fp16. Block: 64 channels x 32 x-positions.
// ---------------------------------------------------------------------------
__global__ __launch_bounds__(256) void transpose_kernel(const float* __restrict__ feat)
{
    __shared__ float tile[64][33];   // [c][x]

    int xt = blockIdx.x * 32;
    int by = blockIdx.y;             // b*H + y
    int b  = by / H_;
    int y  = by % H_;
    int c0 = blockIdx.z * 64;
    int tx = threadIdx.x;
    int ty = threadIdx.y;

    const float* src = feat + ((size_t)(b * C_ + c0) * H_ + y) * W_;
    int  xg  = xt + tx;
    bool xin = xg < W_;

    #pragma unroll
    for (int k = 0; k < 8; k++) {
        int c = ty + k * 8;
        tile[c][tx] = xin ? __ldg(src + (size_t)c * (H_ * W_) + xg) : 0.0f;
    }
    __syncthreads();

    __half* dst = g_feat16 + ((size_t)(b * H_ + y) * W_) * C_ + c0;
    #pragma unroll
    for (int k = 0; k < 4; k++) {
        int xl = ty + k * 8;
        int x  = xt + xl;
        if (x < W_) {
            __half2 v = __floats2half2_rn(tile[2 * tx][xl], tile[2 * tx + 1][xl]);
            *(__half2*)(dst + (size_t)x * C_ + 2 * tx) = v;
        }
    }
}

// ---------------------------------------------------------------------------
// Kernel 2: gather. grid (N): one block per roi, 256 threads = 8 warps.
// One bin per warp per iteration (bins warp, warp+8, ...). Lane covers 8
// channels (uint4 = 16B fp16) -> each corner is one contiguous 512B warp
// request. Fused (offset, half2 weight) tables in smem; staging in fp16.
// ---------------------------------------------------------------------------
__global__ __launch_bounds__(256, 5) void roi_gather_kernel(
    const float* __restrict__ rois,
    float* __restrict__ out)
{
    __shared__ __half sout[NBIN * SOUT_STRIDE];   // [bin][c], 26264 B
    __shared__ int   s_ylo[14], s_yhi[14], s_xlo[14], s_xhi[14];
    __shared__ float s_wy0[14], s_wy1[14], s_wx0[14], s_wx1[14];
    __shared__ int2  s_tab[NBIN * 16];            // .x = corner offset (halves), .y = (w,w) half2 bits

    int n    = blockIdx.x;
    int tid  = threadIdx.x;
    int warp = tid >> 5;
    int lane = tid & 31;

    const float* r = rois + n * 5;
    int   b  = (int)__ldg(r + 0);
    float sx = __ldg(r + 1) * 0.25f - 0.5f;
    float sy = __ldg(r + 2) * 0.25f - 0.5f;
    float ex = __ldg(r + 3) * 0.25f - 0.5f;
    float ey = __ldg(r + 4) * 0.25f - 0.5f;
    float bw = (ex - sx) / (float)OUTW;
    float bh = (ey - sy) / (float)OUTH;

    // --- stage 1: 14 y samples, 14 x samples ---
    if (tid < 14) {
        int s  = tid;
        int ph = s >> 1, iy = s & 1;
        float y = sy + ((float)ph + (0.25f + 0.5f * iy)) * bh;
        bool valid = (y > -1.0f) && (y < (float)H_);
        float y0 = fmaxf(y, 0.0f);
        int ylo = (int)floorf(y0);
        int yhi; float ly;
        if (ylo >= H_ - 1) { ylo = H_ - 1; yhi = H_ - 1; ly = 0.0f; }
        else               { yhi = ylo + 1; ly = y0 - (float)ylo; }
        s_ylo[s] = ylo * (W_ * C_);
        s_yhi[s] = yhi * (W_ * C_);
        s_wy0[s] = valid ? (1.0f - ly) * 0.25f : 0.0f;
        s_wy1[s] = valid ? ly * 0.25f : 0.0f;
    } else if (tid >= 64 && tid < 78) {
        int s  = tid - 64;
        int pw = s >> 1, ix = s & 1;
        float x = sx + ((float)pw + (0.25f + 0.5f * ix)) * bw;
        bool valid = (x > -1.0f) && (x < (float)W_);
        float x0 = fmaxf(x, 0.0f);
        int xlo = (int)floorf(x0);
        int xhi; float lx;
        if (xlo >= W_ - 1) { xlo = W_ - 1; xhi = W_ - 1; lx = 0.0f; }
        else               { xhi = xlo + 1; lx = x0 - (float)xlo; }
        s_xlo[s] = xlo * C_;
        s_xhi[s] = xhi * C_;
        s_wx0[s] = valid ? (1.0f - lx) : 0.0f;
        s_wx1[s] = valid ? lx : 0.0f;
    }
    __syncthreads();

    // --- stage 2: fused per-bin corner tables (49 bins x 16 entries) ---
    for (int e = tid; e < NBIN * 16; e += 256) {
        int bin = e >> 4;
        int j   = e & 15;
        int ph  = bin / OUTW;
        int pw  = bin - ph * OUTW;
        int iy = (j >> 3) & 1, ix = (j >> 2) & 1;
        int cy = (j >> 1) & 1, cx = j & 1;
        int syi = ph * 2 + iy;
        int sxi = pw * 2 + ix;
        int   yoff = cy ? s_yhi[syi] : s_ylo[syi];
        int   xoff = cx ? s_xhi[sxi] : s_xlo[sxi];
        float wy   = cy ? s_wy1[syi] : s_wy0[syi];
        float wx   = cx ? s_wx1[sxi] : s_wx0[sxi];
        __half2 h2 = __float2half2_rn(wy * wx);
        s_tab[e] = make_int2(yoff + xoff, *reinterpret_cast<int*>(&h2));
    }
    __syncthreads();

    // lane -> 8 channels
    int clane = lane * 8;
    const __half* fbase = g_feat16 + (size_t)b * HWC + clane;

    for (int bin = warp; bin < NBIN; bin += 8) {
        const int2* tab = s_tab + (bin << 4);

        float a0 = 0.f, a1 = 0.f, a2 = 0.f, a3 = 0.f;
        float a4 = 0.f, a5 = 0.f, a6 = 0.f, a7 = 0.f;

        #pragma unroll
        for (int s = 0; s < 4; s++) {
            int2 t0 = tab[s * 4 + 0];
            int2 t1 = tab[s * 4 + 1];
            int2 t2 = tab[s * 4 + 2];
            int2 t3 = tab[s * 4 + 3];

            uint4 u0 = *(const uint4*)(fbase + t0.x);
            uint4 u1 = *(const uint4*)(fbase + t1.x);
            uint4 u2 = *(const uint4*)(fbase + t2.x);
            uint4 u3 = *(const uint4*)(fbase + t3.x);

            __half2 w0 = *reinterpret_cast<__half2*>(&t0.y);
            __half2 w1 = *reinterpret_cast<__half2*>(&t1.y);
            __half2 w2 = *reinterpret_cast<__half2*>(&t2.y);
            __half2 w3 = *reinterpret_cast<__half2*>(&t3.y);

            __half2 h0 = __hmul2(w0, *reinterpret_cast<__half2*>(&u0.x));
            __half2 h1 = __hmul2(w0, *reinterpret_cast<__half2*>(&u0.y));
            __half2 h2 = __hmul2(w0, *reinterpret_cast<__half2*>(&u0.z));
            __half2 h3 = __hmul2(w0, *reinterpret_cast<__half2*>(&u0.w));

            h0 = __hfma2(w1, *reinterpret_cast<__half2*>(&u1.x), h0);
            h1 = __hfma2(w1, *reinterpret_cast<__half2*>(&u1.y), h1);
            h2 = __hfma2(w1, *reinterpret_cast<__half2*>(&u1.z), h2);
            h3 = __hfma2(w1, *reinterpret_cast<__half2*>(&u1.w), h3);

            h0 = __hfma2(w2, *reinterpret_cast<__half2*>(&u2.x), h0);
            h1 = __hfma2(w2, *reinterpret_cast<__half2*>(&u2.y), h1);
            h2 = __hfma2(w2, *reinterpret_cast<__half2*>(&u2.z), h2);
            h3 = __hfma2(w2, *reinterpret_cast<__half2*>(&u2.w), h3);

            h0 = __hfma2(w3, *reinterpret_cast<__half2*>(&u3.x), h0);
            h1 = __hfma2(w3, *reinterpret_cast<__half2*>(&u3.y), h1);
            h2 = __hfma2(w3, *reinterpret_cast<__half2*>(&u3.z), h2);
            h3 = __hfma2(w3, *reinterpret_cast<__half2*>(&u3.w), h3);

            float2 f;
            f = __half22float2(h0); a0 += f.x; a1 += f.y;
            f = __half22float2(h1); a2 += f.x; a3 += f.y;
            f = __half22float2(h2); a4 += f.x; a5 += f.y;
            f = __half22float2(h3); a6 += f.x; a7 += f.y;
        }

        // stage fp16 result: [bin][c], two STS.64 (stride 268 keeps 8B alignment)
        __half2 r0 = __floats2half2_rn(a0, a1);
        __half2 r1 = __floats2half2_rn(a2, a3);
        __half2 r2 = __floats2half2_rn(a4, a5);
        __half2 r3 = __floats2half2_rn(a6, a7);
        __half* sp = sout + bin * SOUT_STRIDE + clane;
        *reinterpret_cast<__half2*>(sp)     = r0;
        *reinterpret_cast<__half2*>(sp + 2) = r1;
        *reinterpret_cast<__half2*>(sp + 4) = r2;
        *reinterpret_cast<__half2*>(sp + 6) = r3;
    }
    __syncthreads();

    // coalesced writeout: out[n, c, bin] = sout[bin][c]
    float* o = out + (size_t)n * (C_ * NBIN);
    #pragma unroll 7
    for (int i = tid; i < C_ * NBIN; i += 256) {
        int c   = i / NBIN;
        int bin = i - c * NBIN;
        o[i] = __half2float(sout[bin * SOUT_STRIDE + c]);
    }
}

extern "C" void kernel_launch(void* const* d_in, const int* in_sizes, int n_in,
                              void* d_out, int out_size)
{
    const float* feat = (const float*)d_in[0];
    const float* rois = (const float*)d_in[1];
    float* out = (float*)d_out;

    dim3 tgrid((W_ + 31) / 32, B_ * H_, C_ / 64);
    dim3 tblock(32, 8);
    transpose_kernel<<<tgrid, tblock>>>(feat);

    int n_rois = in_sizes[1] / 5;
    roi_gather_kernel<<<n_rois, 256>>>(rois, out);
}